// round 3
// baseline (speedup 1.0000x reference)
#include <cuda_runtime.h>
#include <cuda_bf16.h>

#define NND 100000
#define NE  1600000
#define NG  128
#define DD  128
#define OUTD 64
#define NL  4
#define BN_EPS 1e-5f

// ---------------- scratch (device globals; no allocation) ----------------
__device__ float g_P[NND * DD];     // pooled = agg + (1+eps)h
__device__ float g_Z[NND * DD];     // gemm output (pre-BN)
__device__ float g_Y[NND * DD];     // MLP hidden activation
__device__ float g_H[NND * DD];     // layer output h
__device__ float g_stats[2 * DD];   // per-channel sum / sumsq
__device__ float g_pg[(NL + 1) * NG * DD];  // graph-pooled hiddens

// ---------------- helpers ----------------
__device__ __forceinline__ void red_add_v4(float* addr, float4 v) {
    asm volatile("red.global.add.v4.f32 [%0], {%1, %2, %3, %4};"
                 :: "l"(addr), "f"(v.x), "f"(v.y), "f"(v.z), "f"(v.w)
                 : "memory");
}

// ---------------- kernels ----------------

// P = (1 + eps[l]) * in     (one float4 per thread)
__global__ void k_init_pooled(const float* __restrict__ in,
                              const float* __restrict__ eps, int l) {
    int idx = blockIdx.x * blockDim.x + threadIdx.x;   // float4 index
    if (idx >= NND * (DD / 4)) return;
    float e = 1.0f + __ldg(&eps[l]);
    float4 v = ((const float4*)in)[idx];
    v.x *= e; v.y *= e; v.z *= e; v.w *= e;
    ((float4*)g_P)[idx] = v;
}

// P[dst] += in[src]  via vector red; one warp per edge
__global__ void k_edge(const float* __restrict__ in,
                       const int* __restrict__ src,
                       const int* __restrict__ dst) {
    int gw = (blockIdx.x * blockDim.x + threadIdx.x) >> 5;
    int lane = threadIdx.x & 31;
    if (gw >= NE) return;
    int s = __ldg(&src[gw]);
    int d = __ldg(&dst[gw]);
    float4 v = ((const float4*)in)[s * (DD / 4) + lane];
    red_add_v4(&g_P[d * DD + lane * 4], v);
}

// Z[M,128] = A[M,128] @ W[128,128] + bias
// tile: 64 rows/block, 256 threads, 8 rows x 4 cols per thread
__global__ void __launch_bounds__(256, 2)
k_gemm(float* __restrict__ out, const float* __restrict__ A,
       const float* __restrict__ W, const float* __restrict__ bias, int M) {
    extern __shared__ float smem[];
    float* Ws = smem;            // [128][128]
    float* At = smem + DD * DD;  // [128][64] transposed A tile

    int t = threadIdx.x;
    int c = t & 31;    // col quad -> cols 4c..4c+3
    int rg = t >> 5;   // row group -> rows 8rg..8rg+7
    int m0 = blockIdx.x * 64;

    // load W (128x128 floats = 4096 float4)
    const float4* W4 = (const float4*)W;
#pragma unroll
    for (int i = 0; i < 16; i++)
        ((float4*)Ws)[t + i * 256] = W4[t + i * 256];

    // load+transpose A tile (64x128 = 2048 float4)
    const float4* A4 = (const float4*)A;
#pragma unroll
    for (int i = 0; i < 8; i++) {
        int fi = t + i * 256;
        int row = fi >> 5;       // 0..63
        int kq = fi & 31;        // k quad
        float4 v = make_float4(0.f, 0.f, 0.f, 0.f);
        int grow = m0 + row;
        if (grow < M) v = A4[grow * 32 + kq];
        int kb = kq * 4;
        At[(kb + 0) * 64 + row] = v.x;
        At[(kb + 1) * 64 + row] = v.y;
        At[(kb + 2) * 64 + row] = v.z;
        At[(kb + 3) * 64 + row] = v.w;
    }
    __syncthreads();

    float acc[8][4];
#pragma unroll
    for (int i = 0; i < 8; i++)
#pragma unroll
        for (int j = 0; j < 4; j++) acc[i][j] = 0.f;

#pragma unroll 4
    for (int k = 0; k < DD; k++) {
        float4 w = *(const float4*)&Ws[k * DD + c * 4];
        float4 a0 = *(const float4*)&At[k * 64 + rg * 8];
        float4 a1 = *(const float4*)&At[k * 64 + rg * 8 + 4];
        float av[8] = {a0.x, a0.y, a0.z, a0.w, a1.x, a1.y, a1.z, a1.w};
#pragma unroll
        for (int i = 0; i < 8; i++) {
            acc[i][0] += av[i] * w.x;
            acc[i][1] += av[i] * w.y;
            acc[i][2] += av[i] * w.z;
            acc[i][3] += av[i] * w.w;
        }
    }

    float4 b = *(const float4*)&bias[c * 4];
#pragma unroll
    for (int i = 0; i < 8; i++) {
        int row = m0 + rg * 8 + i;
        if (row < M) {
            float4 o = make_float4(acc[i][0] + b.x, acc[i][1] + b.y,
                                   acc[i][2] + b.z, acc[i][3] + b.w);
            ((float4*)out)[row * 32 + c] = o;
        }
    }
}

// per-channel sum + sumsq (into pre-zeroed g_stats)
__global__ void k_stats(const float* __restrict__ Z) {
    __shared__ float sbuf[8][DD];
    __shared__ float qbuf[8][DD];
    int t = threadIdx.x;
    int lane = t & 31;
    int w = t >> 5;
    int gwarp = blockIdx.x * 8 + w;
    int stride = gridDim.x * 8;

    float4 s = make_float4(0.f, 0.f, 0.f, 0.f);
    float4 q = make_float4(0.f, 0.f, 0.f, 0.f);
    for (int row = gwarp; row < NND; row += stride) {
        float4 v = ((const float4*)Z)[row * 32 + lane];
        s.x += v.x; s.y += v.y; s.z += v.z; s.w += v.w;
        q.x += v.x * v.x; q.y += v.y * v.y; q.z += v.z * v.z; q.w += v.w * v.w;
    }
    int ch = lane * 4;
    sbuf[w][ch] = s.x; sbuf[w][ch + 1] = s.y; sbuf[w][ch + 2] = s.z; sbuf[w][ch + 3] = s.w;
    qbuf[w][ch] = q.x; qbuf[w][ch + 1] = q.y; qbuf[w][ch + 2] = q.z; qbuf[w][ch + 3] = q.w;
    __syncthreads();
    if (t < DD) {
        float ss = 0.f, qq = 0.f;
#pragma unroll
        for (int i = 0; i < 8; i++) { ss += sbuf[i][t]; qq += qbuf[i][t]; }
        atomicAdd(&g_stats[t], ss);
        atomicAdd(&g_stats[DD + t], qq);
    }
}

// out = relu(g*(Z-mu)*rsqrt(var+eps)+be)
__global__ void k_bnrelu(float* __restrict__ out, const float* __restrict__ Z,
                         const float* __restrict__ gam, const float* __restrict__ bet) {
    __shared__ float sc[DD], sh[DD];
    int t = threadIdx.x;
    if (t < DD) {
        const float inv_n = 1.0f / (float)NND;
        float mu = g_stats[t] * inv_n;
        float var = g_stats[DD + t] * inv_n - mu * mu;
        float s = __ldg(&gam[t]) * rsqrtf(var + BN_EPS);
        sc[t] = s;
        sh[t] = __ldg(&bet[t]) - mu * s;
    }
    __syncthreads();
    int idx = blockIdx.x * blockDim.x + t;   // float4 index
    if (idx >= NND * 32) return;
    int ch = (idx & 31) * 4;
    float4 v = ((const float4*)Z)[idx];
    float4 o;
    o.x = fmaxf(v.x * sc[ch] + sh[ch], 0.f);
    o.y = fmaxf(v.y * sc[ch + 1] + sh[ch + 1], 0.f);
    o.z = fmaxf(v.z * sc[ch + 2] + sh[ch + 2], 0.f);
    o.w = fmaxf(v.w * sc[ch + 3] + sh[ch + 3], 0.f);
    ((float4*)out)[idx] = o;
}

// graph pooling: pg[gid] += h[node]  (warp per node, vector red)
__global__ void k_gpool(float* __restrict__ pg, const float* __restrict__ h,
                        const int* __restrict__ gids) {
    int gw = (blockIdx.x * blockDim.x + threadIdx.x) >> 5;
    int lane = threadIdx.x & 31;
    if (gw >= NND) return;
    int gid = __ldg(&gids[gw]);
    float4 v = ((const float4*)h)[gw * 32 + lane];
    red_add_v4(&pg[gid * DD + lane * 4], v);
}

// score[g][o] = sum_l pg[l][g] @ predW[l][:,o] + sum_l predb[l][o]
__global__ void k_readout(float* __restrict__ out,
                          const float* __restrict__ predW,
                          const float* __restrict__ predb) {
    int g = blockIdx.x;
    int o = threadIdx.x;
    float acc = 0.f;
#pragma unroll
    for (int l = 0; l < NL + 1; l++) {
        const float* pgrow = &g_pg[l * NG * DD + g * DD];
        const float* Wl = &predW[l * DD * OUTD];
        float a = 0.f;
        for (int k = 0; k < DD; k++)
            a += pgrow[k] * __ldg(&Wl[k * OUTD + o]);
        acc += a + __ldg(&predb[l * OUTD + o]);
    }
    out[g * OUTD + o] = acc;
}

// ---------------- launch ----------------
extern "C" void kernel_launch(void* const* d_in, const int* in_sizes, int n_in,
                              void* d_out, int out_size) {
    const float* x     = (const float*)d_in[0];
    const int* esrc    = (const int*)d_in[1];
    const int* edst    = (const int*)d_in[2];
    const int* gids    = (const int*)d_in[3];
    const float* eps   = (const float*)d_in[4];
    const float* W1    = (const float*)d_in[5];
    const float* b1    = (const float*)d_in[6];
    const float* g1    = (const float*)d_in[7];
    const float* be1   = (const float*)d_in[8];
    const float* W2    = (const float*)d_in[9];
    const float* b2    = (const float*)d_in[10];
    const float* g2    = (const float*)d_in[11];
    const float* be2   = (const float*)d_in[12];
    const float* predW = (const float*)d_in[13];
    const float* predb = (const float*)d_in[14];
    float* out = (float*)d_out;

    float *P, *Z, *Y, *H, *stats, *pg;
    cudaGetSymbolAddress((void**)&P, g_P);
    cudaGetSymbolAddress((void**)&Z, g_Z);
    cudaGetSymbolAddress((void**)&Y, g_Y);
    cudaGetSymbolAddress((void**)&H, g_H);
    cudaGetSymbolAddress((void**)&stats, g_stats);
    cudaGetSymbolAddress((void**)&pg, g_pg);

    static bool attr_set = false;
    if (!attr_set) {
        cudaFuncSetAttribute(k_gemm, cudaFuncAttributeMaxDynamicSharedMemorySize,
                             (DD * DD + DD * 64) * (int)sizeof(float));
        attr_set = true;
    }
    const int smem_gemm = (DD * DD + DD * 64) * (int)sizeof(float);

    const int nF4 = NND * (DD / 4);                // 3.2M float4
    const int gridElem = (nF4 + 255) / 256;        // 12500
    const int gridEdge = (NE + 7) / 8;             // warp/edge, 8 warps/block
    const int gridNode = (NND + 7) / 8;            // warp/node
    const int gridGemm = (NND + 63) / 64;

    // zero graph pools, pool layer-0 (= x)
    cudaMemsetAsync(pg, 0, sizeof(float) * (NL + 1) * NG * DD);
    k_gpool<<<gridNode, 256>>>(pg, x, gids);

    const float* hin = x;
    for (int l = 0; l < NL; l++) {
        k_init_pooled<<<gridElem, 256>>>(hin, eps, l);
        k_edge<<<gridEdge, 256>>>(hin, esrc, edst);

        k_gemm<<<gridGemm, 256, smem_gemm>>>(Z, P, W1 + l * DD * DD, b1 + l * DD, NND);
        cudaMemsetAsync(stats, 0, sizeof(float) * 2 * DD);
        k_stats<<<256, 256>>>(Z);
        k_bnrelu<<<gridElem, 256>>>(Y, Z, g1 + l * DD, be1 + l * DD);

        k_gemm<<<gridGemm, 256, smem_gemm>>>(Z, Y, W2 + l * DD * DD, b2 + l * DD, NND);
        cudaMemsetAsync(stats, 0, sizeof(float) * 2 * DD);
        k_stats<<<256, 256>>>(Z);
        k_bnrelu<<<gridElem, 256>>>(H, Z, g2 + l * DD, be2 + l * DD);

        k_gpool<<<gridNode, 256>>>(pg + (l + 1) * NG * DD, H, gids);
        hin = H;
    }

    k_readout<<<NG, OUTD>>>(out, predW, predb);
}

// round 6
// speedup vs baseline: 1.7308x; 1.7308x over previous
#include <cuda_runtime.h>
#include <cuda_bf16.h>

#define NND 100000
#define NE  1600000
#define NG  128
#define DD  128
#define OUTD 64
#define NL  4
#define BN_EPS 1e-5f
#define NT  782                    // ceil(NND/128)
#define AST 132                    // smem row stride in bf16 elems (pad vs bank conflicts)

// ---------------- scratch (device globals; no allocation) ----------------
__device__ float g_P[NND * DD];
__device__ float g_Z[NND * DD];
__device__ float g_Y[NND * DD];
__device__ float g_H[NND * DD];
__device__ float g_stats[2 * DD];
__device__ float g_pg[(NL + 1) * NG * DD];
__device__ int   g_deg[NND];
__device__ int   g_off[NND + 1];
__device__ int   g_cur[NND];
__device__ int   g_esrt[NE];

// ---------------- helpers ----------------
__device__ __forceinline__ void red_add_v4(float* addr, float4 v) {
    asm volatile("red.global.add.v4.f32 [%0], {%1, %2, %3, %4};"
                 :: "l"(addr), "f"(v.x), "f"(v.y), "f"(v.z), "f"(v.w) : "memory");
}
__device__ __forceinline__ unsigned cvt2bf(float lo, float hi) {  // [15:0]=bf16(lo),[31:16]=bf16(hi)
    unsigned r;
    asm("cvt.rn.bf16x2.f32 %0, %1, %2;" : "=r"(r) : "f"(hi), "f"(lo));
    return r;
}
__device__ __forceinline__ void mma16816(float* c, const unsigned* a, const unsigned* b) {
    asm volatile("mma.sync.aligned.m16n8k16.row.col.f32.bf16.bf16.f32 "
                 "{%0,%1,%2,%3}, {%4,%5,%6,%7}, {%8,%9}, {%0,%1,%2,%3};"
                 : "+f"(c[0]), "+f"(c[1]), "+f"(c[2]), "+f"(c[3])
                 : "r"(a[0]), "r"(a[1]), "r"(a[2]), "r"(a[3]), "r"(b[0]), "r"(b[1]));
}

// ---------------- CSR build ----------------
__global__ void k_hist(const int* __restrict__ dst) {
    int e = blockIdx.x * blockDim.x + threadIdx.x;
    if (e < NE) atomicAdd(&g_deg[__ldg(&dst[e])], 1);
}
__global__ void k_scan() {
    __shared__ int sp[1024];
    int t = threadIdx.x;
    int base = t * 98;
    int s = 0;
    for (int i = 0; i < 98; i++) { int j = base + i; if (j < NND) s += g_deg[j]; }
    sp[t] = s;
    __syncthreads();
    for (int o = 1; o < 1024; o <<= 1) {
        int v = (t >= o) ? sp[t - o] : 0;
        __syncthreads();
        sp[t] += v;
        __syncthreads();
    }
    int run = t ? sp[t - 1] : 0;
    for (int i = 0; i < 98; i++) {
        int j = base + i;
        if (j < NND) { g_off[j] = run; g_cur[j] = run; run += g_deg[j]; }
    }
    if (t == 0) g_off[NND] = NE;
}
__global__ void k_scatter(const int* __restrict__ src, const int* __restrict__ dst) {
    int e = blockIdx.x * blockDim.x + threadIdx.x;
    if (e >= NE) return;
    int pos = atomicAdd(&g_cur[__ldg(&dst[e])], 1);
    g_esrt[pos] = __ldg(&src[e]);
}

// ---------------- aggregation: P[d] = (1+eps)h[d] + sum_{e: dst=d} h[src[e]] ----------------
__global__ void k_agg(float* __restrict__ P, const float* __restrict__ h,
                      const float* __restrict__ eps, int l) {
    int gw = (blockIdx.x * blockDim.x + threadIdx.x) >> 5;
    int lane = threadIdx.x & 31;
    if (gw >= NND) return;
    int e0 = __ldg(&g_off[gw]), e1 = __ldg(&g_off[gw + 1]);
    float e = 1.0f + __ldg(&eps[l]);
    float4 v = ((const float4*)h)[gw * 32 + lane];
    float4 acc = make_float4(v.x * e, v.y * e, v.z * e, v.w * e);
    int i = e0;
    for (; i + 1 < e1; i += 2) {
        int s0 = __ldg(&g_esrt[i]), s1 = __ldg(&g_esrt[i + 1]);
        float4 a = ((const float4*)h)[s0 * 32 + lane];
        float4 b = ((const float4*)h)[s1 * 32 + lane];
        acc.x += a.x + b.x; acc.y += a.y + b.y; acc.z += a.z + b.z; acc.w += a.w + b.w;
    }
    if (i < e1) {
        int s0 = __ldg(&g_esrt[i]);
        float4 a = ((const float4*)h)[s0 * 32 + lane];
        acc.x += a.x; acc.y += a.y; acc.z += a.z; acc.w += a.w;
    }
    ((float4*)P)[gw * 32 + lane] = acc;
}

// ---------------- HMMA bf16x3 GEMM + fused column stats ----------------
// Z[NND,128] = A[NND,128] @ W[128,128] + bias; persistent over 128-row tiles.
// smem: Whi/Wlo as B[n][k], Ahi/Alo as A[r][k] (bf16, stride AST).
__global__ void __launch_bounds__(256, 1)
k_mm(float* __restrict__ Z, const float* __restrict__ A,
     const float* __restrict__ W, const float* __restrict__ bias) {
    extern __shared__ unsigned short sm[];
    unsigned short* Whi = sm;
    unsigned short* Wlo = sm + DD * AST;
    unsigned short* Ahi = sm + 2 * DD * AST;
    unsigned short* Alo = sm + 3 * DD * AST;
    __shared__ float colsum[DD], colsq[DD], bias_s[DD];

    const int t = threadIdx.x;
    const int w = t >> 5, lane = t & 31;
    const int g = lane >> 2, q = lane & 3;
    const int wr = (w & 3) * 32;        // warp row base within tile
    const int wc = (w >> 2) * 64;       // warp col base

    // prologue: W split (B[n][k] = W[k][n]), bias, stats
    for (int e = t; e < DD * DD; e += 256) {
        int k = e >> 7, n = e & 127;    // consecutive t -> consecutive n (coalesced gmem)
        float x = __ldg(&W[k * DD + n]);
        unsigned xu = __float_as_uint(x);
        Whi[n * AST + k] = (unsigned short)(xu >> 16);
        unsigned lp = cvt2bf(x - __uint_as_float(xu & 0xffff0000u), 0.f);
        Wlo[n * AST + k] = (unsigned short)(lp & 0xffff);
    }
    if (t < DD) { colsum[t] = 0.f; colsq[t] = 0.f; bias_s[t] = __ldg(&bias[t]); }

    for (int ti = blockIdx.x; ti < NT; ti += gridDim.x) {
        __syncthreads();   // prior tile's compute done (A safe to overwrite); W ready on iter 0

        // load + split A tile [128 rows x 128 k]
#pragma unroll
        for (int i = 0; i < 16; i++) {
            int fi = t + i * 256;            // float4 index: 128*32
            int row = fi >> 5, kq = fi & 31;
            int grow = ti * 128 + row;
            float4 v = make_float4(0.f, 0.f, 0.f, 0.f);
            if (grow < NND) v = ((const float4*)A)[grow * 32 + kq];
            unsigned hx = __byte_perm(__float_as_uint(v.x), __float_as_uint(v.y), 0x7632);
            unsigned hy = __byte_perm(__float_as_uint(v.z), __float_as_uint(v.w), 0x7632);
            unsigned lx = cvt2bf(v.x - __uint_as_float(__float_as_uint(v.x) & 0xffff0000u),
                                 v.y - __uint_as_float(__float_as_uint(v.y) & 0xffff0000u));
            unsigned ly = cvt2bf(v.z - __uint_as_float(__float_as_uint(v.z) & 0xffff0000u),
                                 v.w - __uint_as_float(__float_as_uint(v.w) & 0xffff0000u));
            *(uint2*)&Ahi[row * AST + kq * 4] = make_uint2(hx, hy);
            *(uint2*)&Alo[row * AST + kq * 4] = make_uint2(lx, ly);
        }
        __syncthreads();   // A ready

        // compute: 2 m-tiles x 8 n-tiles of m16n8k16, 3 products
        float c[16][4];
#pragma unroll
        for (int i = 0; i < 16; i++)
#pragma unroll
            for (int j = 0; j < 4; j++) c[i][j] = 0.f;

#pragma unroll
        for (int ks = 0; ks < 8; ks++) {
            int k0 = ks * 16;
            unsigned ah[2][4], al[2][4];
#pragma unroll
            for (int m = 0; m < 2; m++) {
                int r0 = wr + m * 16;
                ah[m][0] = *(unsigned*)&Ahi[(r0 + g) * AST + k0 + q * 2];
                ah[m][1] = *(unsigned*)&Ahi[(r0 + g + 8) * AST + k0 + q * 2];
                ah[m][2] = *(unsigned*)&Ahi[(r0 + g) * AST + k0 + 8 + q * 2];
                ah[m][3] = *(unsigned*)&Ahi[(r0 + g + 8) * AST + k0 + 8 + q * 2];
                al[m][0] = *(unsigned*)&Alo[(r0 + g) * AST + k0 + q * 2];
                al[m][1] = *(unsigned*)&Alo[(r0 + g + 8) * AST + k0 + q * 2];
                al[m][2] = *(unsigned*)&Alo[(r0 + g) * AST + k0 + 8 + q * 2];
                al[m][3] = *(unsigned*)&Alo[(r0 + g + 8) * AST + k0 + 8 + q * 2];
            }
            unsigned bh[8][2], bl[8][2];
#pragma unroll
            for (int n = 0; n < 8; n++) {
                int n0 = wc + n * 8 + g;
                bh[n][0] = *(unsigned*)&Whi[n0 * AST + k0 + q * 2];
                bh[n][1] = *(unsigned*)&Whi[n0 * AST + k0 + 8 + q * 2];
                bl[n][0] = *(unsigned*)&Wlo[n0 * AST + k0 + q * 2];
                bl[n][1] = *(unsigned*)&Wlo[n0 * AST + k0 + 8 + q * 2];
            }
#pragma unroll
            for (int m = 0; m < 2; m++)
#pragma unroll
                for (int n = 0; n < 8; n++) {
                    mma16816(c[m * 8 + n], ah[m], bh[n]);
                    mma16816(c[m * 8 + n], al[m], bh[n]);
                    mma16816(c[m * 8 + n], ah[m], bl[n]);
                }
        }

        // epilogue: bias, store Z, fused column stats
#pragma unroll
        for (int n = 0; n < 8; n++) {
            int col = wc + n * 8 + q * 2;
            float b0 = bias_s[col], b1 = bias_s[col + 1];
            float s0 = 0.f, s1 = 0.f, q0 = 0.f, q1 = 0.f;
#pragma unroll
            for (int m = 0; m < 2; m++) {
                int row0 = ti * 128 + wr + m * 16 + g;
                float* cf = c[m * 8 + n];
                float v0 = cf[0] + b0, v1 = cf[1] + b1;
                float v2 = cf[2] + b0, v3 = cf[3] + b1;
                if (row0 < NND) {
                    *(float2*)&Z[(size_t)row0 * DD + col] = make_float2(v0, v1);
                    s0 += v0; s1 += v1; q0 += v0 * v0; q1 += v1 * v1;
                }
                if (row0 + 8 < NND) {
                    *(float2*)&Z[(size_t)(row0 + 8) * DD + col] = make_float2(v2, v3);
                    s0 += v2; s1 += v3; q0 += v2 * v2; q1 += v3 * v3;
                }
            }
#pragma unroll
            for (int o = 4; o < 32; o <<= 1) {
                s0 += __shfl_xor_sync(0xffffffffu, s0, o);
                s1 += __shfl_xor_sync(0xffffffffu, s1, o);
                q0 += __shfl_xor_sync(0xffffffffu, q0, o);
                q1 += __shfl_xor_sync(0xffffffffu, q1, o);
            }
            if (lane < 4) {
                atomicAdd(&colsum[col], s0);
                atomicAdd(&colsum[col + 1], s1);
                atomicAdd(&colsq[col], q0);
                atomicAdd(&colsq[col + 1], q1);
            }
        }
    }

    __syncthreads();
    if (t < DD) {
        atomicAdd(&g_stats[t], colsum[t]);
        atomicAdd(&g_stats[DD + t], colsq[t]);
    }
}

// ---------------- BN kernels ----------------
__global__ void k_bnrelu(float* __restrict__ out, const float* __restrict__ Z,
                         const float* __restrict__ gam, const float* __restrict__ bet) {
    __shared__ float sc[DD], sh[DD];
    int t = threadIdx.x;
    if (t < DD) {
        const float inv_n = 1.0f / (float)NND;
        float mu = g_stats[t] * inv_n;
        float var = g_stats[DD + t] * inv_n - mu * mu;
        float s = __ldg(&gam[t]) * rsqrtf(var + BN_EPS);
        sc[t] = s;
        sh[t] = __ldg(&bet[t]) - mu * s;
    }
    __syncthreads();
    int idx = blockIdx.x * blockDim.x + t;
    if (idx >= NND * 32) return;
    int ch = (idx & 31) * 4;
    float4 v = ((const float4*)Z)[idx];
    float4 o;
    o.x = fmaxf(v.x * sc[ch] + sh[ch], 0.f);
    o.y = fmaxf(v.y * sc[ch + 1] + sh[ch + 1], 0.f);
    o.z = fmaxf(v.z * sc[ch + 2] + sh[ch + 2], 0.f);
    o.w = fmaxf(v.w * sc[ch + 3] + sh[ch + 3], 0.f);
    ((float4*)out)[idx] = o;
}

// outer BN + relu + graph pooling (red)
__global__ void k_bn2(float* __restrict__ H, float* __restrict__ pg,
                      const float* __restrict__ Z, const float* __restrict__ gam,
                      const float* __restrict__ bet, const int* __restrict__ gids) {
    __shared__ float sc[DD], sh[DD];
    int t = threadIdx.x;
    if (t < DD) {
        const float inv_n = 1.0f / (float)NND;
        float mu = g_stats[t] * inv_n;
        float var = g_stats[DD + t] * inv_n - mu * mu;
        float s = __ldg(&gam[t]) * rsqrtf(var + BN_EPS);
        sc[t] = s;
        sh[t] = __ldg(&bet[t]) - mu * s;
    }
    __syncthreads();
    int idx = blockIdx.x * blockDim.x + t;
    if (idx >= NND * 32) return;
    int row = idx >> 5, ch = (idx & 31) * 4;
    float4 v = ((const float4*)Z)[idx];
    float4 a;
    a.x = fmaxf(v.x * sc[ch] + sh[ch], 0.f);
    a.y = fmaxf(v.y * sc[ch + 1] + sh[ch + 1], 0.f);
    a.z = fmaxf(v.z * sc[ch + 2] + sh[ch + 2], 0.f);
    a.w = fmaxf(v.w * sc[ch + 3] + sh[ch + 3], 0.f);
    ((float4*)H)[idx] = a;
    int gid = __ldg(&gids[row]);
    red_add_v4(&pg[gid * DD + ch], a);
}

__global__ void k_gpool(float* __restrict__ pg, const float* __restrict__ h,
                        const int* __restrict__ gids) {
    int gw = (blockIdx.x * blockDim.x + threadIdx.x) >> 5;
    int lane = threadIdx.x & 31;
    if (gw >= NND) return;
    int gid = __ldg(&gids[gw]);
    float4 v = ((const float4*)h)[gw * 32 + lane];
    red_add_v4(&pg[gid * DD + lane * 4], v);
}

__global__ void k_readout(float* __restrict__ out,
                          const float* __restrict__ predW,
                          const float* __restrict__ predb) {
    int g = blockIdx.x;
    int o = threadIdx.x;
    float acc = 0.f;
#pragma unroll
    for (int l = 0; l < NL + 1; l++) {
        const float* pgrow = &g_pg[l * NG * DD + g * DD];
        const float* Wl = &predW[l * DD * OUTD];
        float a = 0.f;
        for (int k = 0; k < DD; k++)
            a += pgrow[k] * __ldg(&Wl[k * OUTD + o]);
        acc += a + __ldg(&predb[l * OUTD + o]);
    }
    out[g * OUTD + o] = acc;
}

// ---------------- launch ----------------
extern "C" void kernel_launch(void* const* d_in, const int* in_sizes, int n_in,
                              void* d_out, int out_size) {
    const float* x     = (const float*)d_in[0];
    const int* esrc    = (const int*)d_in[1];
    const int* edst    = (const int*)d_in[2];
    const int* gids    = (const int*)d_in[3];
    const float* eps   = (const float*)d_in[4];
    const float* W1    = (const float*)d_in[5];
    const float* b1    = (const float*)d_in[6];
    const float* g1    = (const float*)d_in[7];
    const float* be1   = (const float*)d_in[8];
    const float* W2    = (const float*)d_in[9];
    const float* b2    = (const float*)d_in[10];
    const float* g2    = (const float*)d_in[11];
    const float* be2   = (const float*)d_in[12];
    const float* predW = (const float*)d_in[13];
    const float* predb = (const float*)d_in[14];
    float* out = (float*)d_out;

    float *P, *Z, *Y, *H, *stats, *pg;
    int* deg;
    cudaGetSymbolAddress((void**)&P, g_P);
    cudaGetSymbolAddress((void**)&Z, g_Z);
    cudaGetSymbolAddress((void**)&Y, g_Y);
    cudaGetSymbolAddress((void**)&H, g_H);
    cudaGetSymbolAddress((void**)&stats, g_stats);
    cudaGetSymbolAddress((void**)&pg, g_pg);
    cudaGetSymbolAddress((void**)&deg, g_deg);

    const int smem_mm = 4 * DD * AST * (int)sizeof(unsigned short);  // 135168
    static bool attr_set = false;
    if (!attr_set) {
        cudaFuncSetAttribute(k_mm, cudaFuncAttributeMaxDynamicSharedMemorySize, smem_mm);
        attr_set = true;
    }

    const int gridElem = (NND * 32 + 255) / 256;
    const int gridEdge = (NE + 255) / 256;
    const int gridNode = (NND + 7) / 8;

    // CSR build (once; shared by all 4 layers)
    cudaMemsetAsync(deg, 0, sizeof(int) * NND);
    k_hist<<<gridEdge, 256>>>(edst);
    k_scan<<<1, 1024>>>();
    k_scatter<<<gridEdge, 256>>>(esrc, edst);

    // layer-0 graph pooling
    cudaMemsetAsync(pg, 0, sizeof(float) * (NL + 1) * NG * DD);
    k_gpool<<<gridNode, 256>>>(pg, x, gids);

    const float* hin = x;
    for (int l = 0; l < NL; l++) {
        k_agg<<<(NND + 7) / 8, 256>>>(P, hin, eps, l);

        cudaMemsetAsync(stats, 0, sizeof(float) * 2 * DD);
        k_mm<<<148, 256, smem_mm>>>(Z, P, W1 + l * DD * DD, b1 + l * DD);
        k_bnrelu<<<gridElem, 256>>>(Y, Z, g1 + l * DD, be1 + l * DD);

        cudaMemsetAsync(stats, 0, sizeof(float) * 2 * DD);
        k_mm<<<148, 256, smem_mm>>>(Z, Y, W2 + l * DD * DD, b2 + l * DD);
        k_bn2<<<gridElem, 256>>>(H, pg + (l + 1) * NG * DD, Z,
                                 g2 + l * DD, be2 + l * DD, gids);
        hin = H;
    }

    k_readout<<<NG, OUTD>>>(out, predW, predb);
}

// round 7
// speedup vs baseline: 2.0238x; 1.1693x over previous
#include <cuda_runtime.h>
#include <cuda_bf16.h>

#define NND 100000
#define NE  1600000
#define NG  128
#define DD  128
#define OUTD 64
#define NL  4
#define BN_EPS 1e-5f
#define NT  782                    // ceil(NND/128)
#define AST 132                    // smem row stride in bf16 elems (pad vs bank conflicts)

// ---------------- scratch (device globals; no allocation) ----------------
__device__ float g_P[NND * DD];
__device__ float g_Z[NND * DD];     // GEMM1 output
__device__ float g_Z2[NND * DD];    // GEMM2 output
__device__ float g_H[NND * DD];
__device__ float g_stats[2][2 * DD];   // two slots: sum / sumsq
__device__ float g_pg[(NL + 1) * NG * DD];
__device__ int   g_deg[NND];
__device__ int   g_off[NND + 1];
__device__ int   g_cur[NND];
__device__ int   g_esrt[NE];

// ---------------- helpers ----------------
__device__ __forceinline__ void red_add_v4(float* addr, float4 v) {
    asm volatile("red.global.add.v4.f32 [%0], {%1, %2, %3, %4};"
                 :: "l"(addr), "f"(v.x), "f"(v.y), "f"(v.z), "f"(v.w) : "memory");
}
__device__ __forceinline__ unsigned cvt2bf(float lo, float hi) {  // [15:0]=bf16(lo),[31:16]=bf16(hi)
    unsigned r;
    asm("cvt.rn.bf16x2.f32 %0, %1, %2;" : "=r"(r) : "f"(hi), "f"(lo));
    return r;
}
__device__ __forceinline__ void mma16816(float* c, const unsigned* a, const unsigned* b) {
    asm volatile("mma.sync.aligned.m16n8k16.row.col.f32.bf16.bf16.f32 "
                 "{%0,%1,%2,%3}, {%4,%5,%6,%7}, {%8,%9}, {%0,%1,%2,%3};"
                 : "+f"(c[0]), "+f"(c[1]), "+f"(c[2]), "+f"(c[3])
                 : "r"(a[0]), "r"(a[1]), "r"(a[2]), "r"(a[3]), "r"(b[0]), "r"(b[1]));
}

// ---------------- CSR build ----------------
__global__ void k_hist(const int* __restrict__ dst) {
    int e = blockIdx.x * blockDim.x + threadIdx.x;
    if (e < NE) atomicAdd(&g_deg[__ldg(&dst[e])], 1);
}
__global__ void k_scan() {
    __shared__ int sp[1024];
    int t = threadIdx.x;
    int base = t * 98;
    int s = 0;
    for (int i = 0; i < 98; i++) { int j = base + i; if (j < NND) s += g_deg[j]; }
    sp[t] = s;
    __syncthreads();
    for (int o = 1; o < 1024; o <<= 1) {
        int v = (t >= o) ? sp[t - o] : 0;
        __syncthreads();
        sp[t] += v;
        __syncthreads();
    }
    int run = t ? sp[t - 1] : 0;
    for (int i = 0; i < 98; i++) {
        int j = base + i;
        if (j < NND) { g_off[j] = run; g_cur[j] = run; run += g_deg[j]; }
    }
    if (t == 0) g_off[NND] = NE;
}
__global__ void k_scatter(const int* __restrict__ src, const int* __restrict__ dst) {
    int e = blockIdx.x * blockDim.x + threadIdx.x;
    if (e >= NE) return;
    int pos = atomicAdd(&g_cur[__ldg(&dst[e])], 1);
    g_esrt[pos] = __ldg(&src[e]);
}

// ---------------- aggregation: P[d] = (1+eps)h[d] + sum_{e: dst=d} h[src[e]] ----------------
__global__ void k_agg(float* __restrict__ P, const float* __restrict__ h,
                      const float* __restrict__ eps, int l) {
    int gw = (blockIdx.x * blockDim.x + threadIdx.x) >> 5;
    int lane = threadIdx.x & 31;
    if (gw >= NND) return;
    int e0 = __ldg(&g_off[gw]), e1 = __ldg(&g_off[gw + 1]);
    float e = 1.0f + __ldg(&eps[l]);
    float4 v = ((const float4*)h)[gw * 32 + lane];
    float4 acc = make_float4(v.x * e, v.y * e, v.z * e, v.w * e);
    int i = e0;
    for (; i + 1 < e1; i += 2) {
        int s0 = __ldg(&g_esrt[i]), s1 = __ldg(&g_esrt[i + 1]);
        float4 a = ((const float4*)h)[s0 * 32 + lane];
        float4 b = ((const float4*)h)[s1 * 32 + lane];
        acc.x += a.x + b.x; acc.y += a.y + b.y; acc.z += a.z + b.z; acc.w += a.w + b.w;
    }
    if (i < e1) {
        int s0 = __ldg(&g_esrt[i]);
        float4 a = ((const float4*)h)[s0 * 32 + lane];
        acc.x += a.x; acc.y += a.y; acc.z += a.z; acc.w += a.w;
    }
    ((float4*)P)[gw * 32 + lane] = acc;
}

// ---------------- HMMA bf16x3 GEMM + fused column stats (+ optional fused input-BN) ----
// Z = BNrelu?(A) @ W + bias.  If gam != null: A is normalized with statsIn/gam/bet + relu
// during the fp32->bf16 split.  Column stats of the OUTPUT accumulate into statsOut.
__global__ void __launch_bounds__(256, 1)
k_mm(float* __restrict__ Z, const float* __restrict__ A,
     const float* __restrict__ W, const float* __restrict__ bias,
     const float* __restrict__ gam, const float* __restrict__ bet,
     const float* __restrict__ statsIn, float* __restrict__ statsOut) {
    extern __shared__ unsigned short sm[];
    unsigned short* Whi = sm;
    unsigned short* Wlo = sm + DD * AST;
    unsigned short* Ahi = sm + 2 * DD * AST;
    unsigned short* Alo = sm + 3 * DD * AST;
    __shared__ float colsum[DD], colsq[DD], bias_s[DD], scA[DD], shA[DD];

    const int t = threadIdx.x;
    const int w = t >> 5, lane = t & 31;
    const int g = lane >> 2, q = lane & 3;
    const int wr = (w & 3) * 32;        // warp row base within tile
    const int wc = (w >> 2) * 64;       // warp col base
    const bool doBN = (gam != nullptr);

    // prologue: W split (B[n][k] = W[k][n]), bias, stats, optional input-BN coefs
    for (int e = t; e < DD * DD; e += 256) {
        int k = e >> 7, n = e & 127;
        float x = __ldg(&W[k * DD + n]);
        unsigned xu = __float_as_uint(x);
        Whi[n * AST + k] = (unsigned short)(xu >> 16);
        unsigned lp = cvt2bf(x - __uint_as_float(xu & 0xffff0000u), 0.f);
        Wlo[n * AST + k] = (unsigned short)(lp & 0xffff);
    }
    if (t < DD) {
        colsum[t] = 0.f; colsq[t] = 0.f; bias_s[t] = __ldg(&bias[t]);
        if (doBN) {
            const float inv_n = 1.0f / (float)NND;
            float mu = statsIn[t] * inv_n;
            float var = statsIn[DD + t] * inv_n - mu * mu;
            float s = __ldg(&gam[t]) * rsqrtf(var + BN_EPS);
            scA[t] = s;
            shA[t] = __ldg(&bet[t]) - mu * s;
        }
    }

    for (int ti = blockIdx.x; ti < NT; ti += gridDim.x) {
        __syncthreads();   // prior tile's compute done; prologue visible on iter 0

        // load (+ optional BN+relu) + split A tile [128 rows x 128 k]
#pragma unroll
        for (int i = 0; i < 16; i++) {
            int fi = t + i * 256;
            int row = fi >> 5, kq = fi & 31;
            int grow = ti * 128 + row;
            float4 v = make_float4(0.f, 0.f, 0.f, 0.f);
            if (grow < NND) {
                v = ((const float4*)A)[grow * 32 + kq];
                if (doBN) {
                    int ch = kq * 4;
                    v.x = fmaxf(v.x * scA[ch] + shA[ch], 0.f);
                    v.y = fmaxf(v.y * scA[ch + 1] + shA[ch + 1], 0.f);
                    v.z = fmaxf(v.z * scA[ch + 2] + shA[ch + 2], 0.f);
                    v.w = fmaxf(v.w * scA[ch + 3] + shA[ch + 3], 0.f);
                }
            }
            unsigned hx = __byte_perm(__float_as_uint(v.x), __float_as_uint(v.y), 0x7632);
            unsigned hy = __byte_perm(__float_as_uint(v.z), __float_as_uint(v.w), 0x7632);
            unsigned lx = cvt2bf(v.x - __uint_as_float(__float_as_uint(v.x) & 0xffff0000u),
                                 v.y - __uint_as_float(__float_as_uint(v.y) & 0xffff0000u));
            unsigned ly = cvt2bf(v.z - __uint_as_float(__float_as_uint(v.z) & 0xffff0000u),
                                 v.w - __uint_as_float(__float_as_uint(v.w) & 0xffff0000u));
            *(uint2*)&Ahi[row * AST + kq * 4] = make_uint2(hx, hy);
            *(uint2*)&Alo[row * AST + kq * 4] = make_uint2(lx, ly);
        }
        __syncthreads();   // A ready

        float c[16][4];
#pragma unroll
        for (int i = 0; i < 16; i++)
#pragma unroll
            for (int j = 0; j < 4; j++) c[i][j] = 0.f;

#pragma unroll
        for (int ks = 0; ks < 8; ks++) {
            int k0 = ks * 16;
            unsigned ah[2][4], al[2][4];
#pragma unroll
            for (int m = 0; m < 2; m++) {
                int r0 = wr + m * 16;
                ah[m][0] = *(unsigned*)&Ahi[(r0 + g) * AST + k0 + q * 2];
                ah[m][1] = *(unsigned*)&Ahi[(r0 + g + 8) * AST + k0 + q * 2];
                ah[m][2] = *(unsigned*)&Ahi[(r0 + g) * AST + k0 + 8 + q * 2];
                ah[m][3] = *(unsigned*)&Ahi[(r0 + g + 8) * AST + k0 + 8 + q * 2];
                al[m][0] = *(unsigned*)&Alo[(r0 + g) * AST + k0 + q * 2];
                al[m][1] = *(unsigned*)&Alo[(r0 + g + 8) * AST + k0 + q * 2];
                al[m][2] = *(unsigned*)&Alo[(r0 + g) * AST + k0 + 8 + q * 2];
                al[m][3] = *(unsigned*)&Alo[(r0 + g + 8) * AST + k0 + 8 + q * 2];
            }
            unsigned bh[8][2], bl[8][2];
#pragma unroll
            for (int n = 0; n < 8; n++) {
                int n0 = wc + n * 8 + g;
                bh[n][0] = *(unsigned*)&Whi[n0 * AST + k0 + q * 2];
                bh[n][1] = *(unsigned*)&Whi[n0 * AST + k0 + 8 + q * 2];
                bl[n][0] = *(unsigned*)&Wlo[n0 * AST + k0 + q * 2];
                bl[n][1] = *(unsigned*)&Wlo[n0 * AST + k0 + 8 + q * 2];
            }
#pragma unroll
            for (int m = 0; m < 2; m++)
#pragma unroll
                for (int n = 0; n < 8; n++) {
                    mma16816(c[m * 8 + n], ah[m], bh[n]);
                    mma16816(c[m * 8 + n], al[m], bh[n]);
                    mma16816(c[m * 8 + n], ah[m], bl[n]);
                }
        }

        // epilogue: bias, store Z, fused output column stats
#pragma unroll
        for (int n = 0; n < 8; n++) {
            int col = wc + n * 8 + q * 2;
            float b0 = bias_s[col], b1 = bias_s[col + 1];
            float s0 = 0.f, s1 = 0.f, q0 = 0.f, q1 = 0.f;
#pragma unroll
            for (int m = 0; m < 2; m++) {
                int row0 = ti * 128 + wr + m * 16 + g;
                float* cf = c[m * 8 + n];
                float v0 = cf[0] + b0, v1 = cf[1] + b1;
                float v2 = cf[2] + b0, v3 = cf[3] + b1;
                if (row0 < NND) {
                    *(float2*)&Z[(size_t)row0 * DD + col] = make_float2(v0, v1);
                    s0 += v0; s1 += v1; q0 += v0 * v0; q1 += v1 * v1;
                }
                if (row0 + 8 < NND) {
                    *(float2*)&Z[(size_t)(row0 + 8) * DD + col] = make_float2(v2, v3);
                    s0 += v2; s1 += v3; q0 += v2 * v2; q1 += v3 * v3;
                }
            }
#pragma unroll
            for (int o = 4; o < 32; o <<= 1) {
                s0 += __shfl_xor_sync(0xffffffffu, s0, o);
                s1 += __shfl_xor_sync(0xffffffffu, s1, o);
                q0 += __shfl_xor_sync(0xffffffffu, q0, o);
                q1 += __shfl_xor_sync(0xffffffffu, q1, o);
            }
            if (lane < 4) {
                atomicAdd(&colsum[col], s0);
                atomicAdd(&colsum[col + 1], s1);
                atomicAdd(&colsq[col], q0);
                atomicAdd(&colsq[col + 1], q1);
            }
        }
    }

    __syncthreads();
    if (t < DD) {
        atomicAdd(&statsOut[t], colsum[t]);
        atomicAdd(&statsOut[DD + t], colsq[t]);
    }
}

// ---------------- outer BN + relu + SEGMENTED graph pooling ----------------
// warp owns 32 consecutive rows; lane owns one float4 column; red only on gid change.
__global__ void k_bn2(float* __restrict__ H, float* __restrict__ pg,
                      const float* __restrict__ Z, const float* __restrict__ gam,
                      const float* __restrict__ bet, const float* __restrict__ stats,
                      const int* __restrict__ gids) {
    __shared__ float sc[DD], sh[DD];
    int t = threadIdx.x;
    if (t < DD) {
        const float inv_n = 1.0f / (float)NND;
        float mu = stats[t] * inv_n;
        float var = stats[DD + t] * inv_n - mu * mu;
        float s = __ldg(&gam[t]) * rsqrtf(var + BN_EPS);
        sc[t] = s;
        sh[t] = __ldg(&bet[t]) - mu * s;
    }
    __syncthreads();
    int warp = (blockIdx.x * blockDim.x + t) >> 5;
    int lane = t & 31;
    int r0 = warp * 32;
    if (r0 >= NND) return;
    int r1 = min(r0 + 32, NND);
    int ch = lane * 4;
    float c0 = sc[ch], c1 = sc[ch + 1], c2 = sc[ch + 2], c3 = sc[ch + 3];
    float h0 = sh[ch], h1 = sh[ch + 1], h2 = sh[ch + 2], h3 = sh[ch + 3];
    int cur = __ldg(&gids[r0]);
    float4 acc = make_float4(0.f, 0.f, 0.f, 0.f);
    for (int r = r0; r < r1; r++) {
        int gid = __ldg(&gids[r]);
        if (gid != cur) {
            red_add_v4(&pg[cur * DD + ch], acc);
            acc = make_float4(0.f, 0.f, 0.f, 0.f);
            cur = gid;
        }
        float4 v = ((const float4*)Z)[r * 32 + lane];
        float4 a;
        a.x = fmaxf(v.x * c0 + h0, 0.f);
        a.y = fmaxf(v.y * c1 + h1, 0.f);
        a.z = fmaxf(v.z * c2 + h2, 0.f);
        a.w = fmaxf(v.w * c3 + h3, 0.f);
        ((float4*)H)[r * 32 + lane] = a;
        acc.x += a.x; acc.y += a.y; acc.z += a.z; acc.w += a.w;
    }
    red_add_v4(&pg[cur * DD + ch], acc);
}

// segmented pooling for layer-0 (h = x)
__global__ void k_gpool(float* __restrict__ pg, const float* __restrict__ h,
                        const int* __restrict__ gids) {
    int warp = (blockIdx.x * blockDim.x + threadIdx.x) >> 5;
    int lane = threadIdx.x & 31;
    int r0 = warp * 32;
    if (r0 >= NND) return;
    int r1 = min(r0 + 32, NND);
    int ch = lane * 4;
    int cur = __ldg(&gids[r0]);
    float4 acc = make_float4(0.f, 0.f, 0.f, 0.f);
    for (int r = r0; r < r1; r++) {
        int gid = __ldg(&gids[r]);
        if (gid != cur) {
            red_add_v4(&pg[cur * DD + ch], acc);
            acc = make_float4(0.f, 0.f, 0.f, 0.f);
            cur = gid;
        }
        float4 v = ((const float4*)h)[r * 32 + lane];
        acc.x += v.x; acc.y += v.y; acc.z += v.z; acc.w += v.w;
    }
    red_add_v4(&pg[cur * DD + ch], acc);
}

__global__ void k_readout(float* __restrict__ out,
                          const float* __restrict__ predW,
                          const float* __restrict__ predb) {
    int g = blockIdx.x;
    int o = threadIdx.x;
    float acc = 0.f;
#pragma unroll
    for (int l = 0; l < NL + 1; l++) {
        const float* pgrow = &g_pg[l * NG * DD + g * DD];
        const float* Wl = &predW[l * DD * OUTD];
        float a = 0.f;
        for (int k = 0; k < DD; k++)
            a += pgrow[k] * __ldg(&Wl[k * OUTD + o]);
        acc += a + __ldg(&predb[l * OUTD + o]);
    }
    out[g * OUTD + o] = acc;
}

// ---------------- launch ----------------
extern "C" void kernel_launch(void* const* d_in, const int* in_sizes, int n_in,
                              void* d_out, int out_size) {
    const float* x     = (const float*)d_in[0];
    const int* esrc    = (const int*)d_in[1];
    const int* edst    = (const int*)d_in[2];
    const int* gids    = (const int*)d_in[3];
    const float* eps   = (const float*)d_in[4];
    const float* W1    = (const float*)d_in[5];
    const float* b1    = (const float*)d_in[6];
    const float* g1    = (const float*)d_in[7];
    const float* be1   = (const float*)d_in[8];
    const float* W2    = (const float*)d_in[9];
    const float* b2    = (const float*)d_in[10];
    const float* g2    = (const float*)d_in[11];
    const float* be2   = (const float*)d_in[12];
    const float* predW = (const float*)d_in[13];
    const float* predb = (const float*)d_in[14];
    float* out = (float*)d_out;

    float *P, *Z, *Z2, *H, *stats, *pg;
    int* deg;
    cudaGetSymbolAddress((void**)&P, g_P);
    cudaGetSymbolAddress((void**)&Z, g_Z);
    cudaGetSymbolAddress((void**)&Z2, g_Z2);
    cudaGetSymbolAddress((void**)&H, g_H);
    cudaGetSymbolAddress((void**)&stats, g_stats);
    cudaGetSymbolAddress((void**)&pg, g_pg);
    cudaGetSymbolAddress((void**)&deg, g_deg);
    float* s0 = stats;
    float* s1 = stats + 2 * DD;

    const int smem_mm = 4 * DD * AST * (int)sizeof(unsigned short);  // 135168
    static bool attr_set = false;
    if (!attr_set) {
        cudaFuncSetAttribute(k_mm, cudaFuncAttributeMaxDynamicSharedMemorySize, smem_mm);
        attr_set = true;
    }

    const int gridEdge = (NE + 255) / 256;
    const int nWarps = (NND + 31) / 32;                 // segmented pooling warps
    const int gridSeg = (nWarps * 32 + 255) / 256;      // 391 blocks

    // CSR build (once; shared by all 4 layers)
    cudaMemsetAsync(deg, 0, sizeof(int) * NND);
    k_hist<<<gridEdge, 256>>>(edst);
    k_scan<<<1, 1024>>>();
    k_scatter<<<gridEdge, 256>>>(esrc, edst);

    // layer-0 graph pooling (segmented)
    cudaMemsetAsync(pg, 0, sizeof(float) * (NL + 1) * NG * DD);
    k_gpool<<<gridSeg, 256>>>(pg, x, gids);

    const float* hin = x;
    for (int l = 0; l < NL; l++) {
        k_agg<<<(NND + 7) / 8, 256>>>(P, hin, eps, l);

        cudaMemsetAsync(s0, 0, sizeof(float) * 2 * DD);
        k_mm<<<148, 256, smem_mm>>>(Z, P, W1 + l * DD * DD, b1 + l * DD,
                                    nullptr, nullptr, nullptr, s0);

        cudaMemsetAsync(s1, 0, sizeof(float) * 2 * DD);
        k_mm<<<148, 256, smem_mm>>>(Z2, Z, W2 + l * DD * DD, b2 + l * DD,
                                    g1 + l * DD, be1 + l * DD, s0, s1);

        k_bn2<<<gridSeg, 256>>>(H, pg + (l + 1) * NG * DD, Z2,
                                g2 + l * DD, be2 + l * DD, s1, gids);
        hin = H;
    }

    k_readout<<<NG, OUTD>>>(out, predW, predb);
}

// round 8
// speedup vs baseline: 2.1255x; 1.0503x over previous
#include <cuda_runtime.h>
#include <cuda_bf16.h>

#define NND 100000
#define NE  1600000
#define NG  128
#define DD  128
#define OUTD 64
#define NL  4
#define BN_EPS 1e-5f
#define NT  782                    // ceil(NND/128)
#define AST 132                    // smem row stride in bf16 elems (pad vs bank conflicts)

// ---------------- scratch (device globals; no allocation) ----------------
__device__ float g_P[NND * DD];
__device__ float g_Z[NND * DD];     // GEMM1 output
__device__ float g_Z2[NND * DD];    // GEMM2 output
__device__ float g_stats[2][2 * DD];   // two slots: sum / sumsq
__device__ float g_pg[(NL + 1) * NG * DD];
__device__ int   g_deg[NND];
__device__ int   g_off[NND + 1];
__device__ int   g_cur[NND];
__device__ int   g_esrt[NE];

// ---------------- helpers ----------------
__device__ __forceinline__ void red_add_v4(float* addr, float4 v) {
    asm volatile("red.global.add.v4.f32 [%0], {%1, %2, %3, %4};"
                 :: "l"(addr), "f"(v.x), "f"(v.y), "f"(v.z), "f"(v.w) : "memory");
}
__device__ __forceinline__ unsigned cvt2bf(float lo, float hi) {  // [15:0]=bf16(lo),[31:16]=bf16(hi)
    unsigned r;
    asm("cvt.rn.bf16x2.f32 %0, %1, %2;" : "=r"(r) : "f"(hi), "f"(lo));
    return r;
}
__device__ __forceinline__ void mma16816(float* c, const unsigned* a, const unsigned* b) {
    asm volatile("mma.sync.aligned.m16n8k16.row.col.f32.bf16.bf16.f32 "
                 "{%0,%1,%2,%3}, {%4,%5,%6,%7}, {%8,%9}, {%0,%1,%2,%3};"
                 : "+f"(c[0]), "+f"(c[1]), "+f"(c[2]), "+f"(c[3])
                 : "r"(a[0]), "r"(a[1]), "r"(a[2]), "r"(a[3]), "r"(b[0]), "r"(b[1]));
}
__device__ __forceinline__ void cpasync16(unsigned saddr, const void* g, int sz) {
    asm volatile("cp.async.cg.shared.global [%0], [%1], 16, %2;"
                 :: "r"(saddr), "l"(g), "r"(sz) : "memory");
}
#define CP_COMMIT() asm volatile("cp.async.commit_group;" ::: "memory")
#define CP_WAIT0()  asm volatile("cp.async.wait_group 0;" ::: "memory")

// ---------------- CSR build ----------------
__global__ void k_hist(const int* __restrict__ dst) {
    int e = blockIdx.x * blockDim.x + threadIdx.x;
    if (e < NE) atomicAdd(&g_deg[__ldg(&dst[e])], 1);
}
__global__ void k_scan() {
    __shared__ int sp[1024];
    int t = threadIdx.x;
    int base = t * 98;
    int s = 0;
    for (int i = 0; i < 98; i++) { int j = base + i; if (j < NND) s += g_deg[j]; }
    sp[t] = s;
    __syncthreads();
    for (int o = 1; o < 1024; o <<= 1) {
        int v = (t >= o) ? sp[t - o] : 0;
        __syncthreads();
        sp[t] += v;
        __syncthreads();
    }
    int run = t ? sp[t - 1] : 0;
    for (int i = 0; i < 98; i++) {
        int j = base + i;
        if (j < NND) { g_off[j] = run; g_cur[j] = run; run += g_deg[j]; }
    }
    if (t == 0) g_off[NND] = NE;
}
__global__ void k_scatter(const int* __restrict__ src, const int* __restrict__ dst) {
    int e = blockIdx.x * blockDim.x + threadIdx.x;
    if (e >= NE) return;
    int pos = atomicAdd(&g_cur[__ldg(&dst[e])], 1);
    g_esrt[pos] = __ldg(&src[e]);
}

// ---- aggregation with fused input BN+relu:
// h[r] = doBN ? relu(Z[r]*sc+sh) : Z[r];  P[d] = (1+eps)h[d] + sum h[src]
__global__ void k_agg(float* __restrict__ P, const float* __restrict__ Zs,
                      const float* __restrict__ eps, int l,
                      const float* __restrict__ gam, const float* __restrict__ bet,
                      const float* __restrict__ stats) {
    __shared__ float sc[DD], sh[DD];
    int t = threadIdx.x;
    const bool doBN = (gam != nullptr);
    if (doBN && t < DD) {
        const float inv_n = 1.0f / (float)NND;
        float mu = stats[t] * inv_n;
        float var = stats[DD + t] * inv_n - mu * mu;
        float s = __ldg(&gam[t]) * rsqrtf(var + BN_EPS);
        sc[t] = s;
        sh[t] = __ldg(&bet[t]) - mu * s;
    }
    __syncthreads();
    int gw = (blockIdx.x * blockDim.x + t) >> 5;
    int lane = t & 31;
    if (gw >= NND) return;
    int ch = lane * 4;
    float c0 = 1.f, c1 = 1.f, c2 = 1.f, c3 = 1.f, h0 = 0.f, h1 = 0.f, h2 = 0.f, h3 = 0.f;
    if (doBN) {
        c0 = sc[ch]; c1 = sc[ch + 1]; c2 = sc[ch + 2]; c3 = sc[ch + 3];
        h0 = sh[ch]; h1 = sh[ch + 1]; h2 = sh[ch + 2]; h3 = sh[ch + 3];
    }
    int e0 = __ldg(&g_off[gw]), e1 = __ldg(&g_off[gw + 1]);
    float e = 1.0f + __ldg(&eps[l]);

    float4 v = ((const float4*)Zs)[gw * 32 + lane];
    if (doBN) {
        v.x = fmaxf(v.x * c0 + h0, 0.f); v.y = fmaxf(v.y * c1 + h1, 0.f);
        v.z = fmaxf(v.z * c2 + h2, 0.f); v.w = fmaxf(v.w * c3 + h3, 0.f);
    }
    float4 acc = make_float4(v.x * e, v.y * e, v.z * e, v.w * e);
    int i = e0;
    if (doBN) {
        for (; i + 1 < e1; i += 2) {
            int s0 = __ldg(&g_esrt[i]), s1 = __ldg(&g_esrt[i + 1]);
            float4 a = ((const float4*)Zs)[s0 * 32 + lane];
            float4 b = ((const float4*)Zs)[s1 * 32 + lane];
            acc.x += fmaxf(a.x * c0 + h0, 0.f) + fmaxf(b.x * c0 + h0, 0.f);
            acc.y += fmaxf(a.y * c1 + h1, 0.f) + fmaxf(b.y * c1 + h1, 0.f);
            acc.z += fmaxf(a.z * c2 + h2, 0.f) + fmaxf(b.z * c2 + h2, 0.f);
            acc.w += fmaxf(a.w * c3 + h3, 0.f) + fmaxf(b.w * c3 + h3, 0.f);
        }
        if (i < e1) {
            int s0 = __ldg(&g_esrt[i]);
            float4 a = ((const float4*)Zs)[s0 * 32 + lane];
            acc.x += fmaxf(a.x * c0 + h0, 0.f); acc.y += fmaxf(a.y * c1 + h1, 0.f);
            acc.z += fmaxf(a.z * c2 + h2, 0.f); acc.w += fmaxf(a.w * c3 + h3, 0.f);
        }
    } else {
        for (; i + 1 < e1; i += 2) {
            int s0 = __ldg(&g_esrt[i]), s1 = __ldg(&g_esrt[i + 1]);
            float4 a = ((const float4*)Zs)[s0 * 32 + lane];
            float4 b = ((const float4*)Zs)[s1 * 32 + lane];
            acc.x += a.x + b.x; acc.y += a.y + b.y; acc.z += a.z + b.z; acc.w += a.w + b.w;
        }
        if (i < e1) {
            int s0 = __ldg(&g_esrt[i]);
            float4 a = ((const float4*)Zs)[s0 * 32 + lane];
            acc.x += a.x; acc.y += a.y; acc.z += a.z; acc.w += a.w;
        }
    }
    ((float4*)P)[gw * 32 + lane] = acc;
}

// ---------------- HMMA bf16x3 GEMM, cp.async-staged, fused stats & input-BN ----------
__global__ void __launch_bounds__(256, 1)
k_mm(float* __restrict__ Z, const float* __restrict__ A,
     const float* __restrict__ W, const float* __restrict__ bias,
     const float* __restrict__ gam, const float* __restrict__ bet,
     const float* __restrict__ statsIn, float* __restrict__ statsOut) {
    extern __shared__ unsigned short sm[];
    unsigned short* Whi = sm;
    unsigned short* Wlo = sm + DD * AST;
    unsigned short* Ahi = sm + 2 * DD * AST;
    unsigned short* Alo = sm + 3 * DD * AST;
    float* Sg = (float*)(sm + 4 * DD * AST);        // 64KB fp32 staging
    __shared__ float colsum[DD], colsq[DD], bias_s[DD], scA[DD], shA[DD];

    const int t = threadIdx.x;
    const int w = t >> 5, lane = t & 31;
    const int g = lane >> 2, q = lane & 3;
    const int wr = (w & 3) * 32;
    const int wc = (w >> 2) * 64;
    const bool doBN = (gam != nullptr);
    const unsigned sgBase = (unsigned)__cvta_generic_to_shared(Sg);

    // kick off first tile fetch before the W prologue
    {
        int ti = blockIdx.x;
#pragma unroll
        for (int i = 0; i < 16; i++) {
            int fi = t + i * 256;
            int row = fi >> 5, kq = fi & 31;
            int grow = ti * 128 + row;
            bool valid = grow < NND;
            const float4* gp = (const float4*)A + ((size_t)(valid ? grow : 0) * 32 + kq);
            cpasync16(sgBase + fi * 16, gp, valid ? 16 : 0);
        }
        CP_COMMIT();
    }

    // prologue: W split (B[n][k] = W[k][n]), bias, stats, optional input-BN coefs
    for (int e = t; e < DD * DD; e += 256) {
        int k = e >> 7, n = e & 127;
        float x = __ldg(&W[k * DD + n]);
        unsigned xu = __float_as_uint(x);
        Whi[n * AST + k] = (unsigned short)(xu >> 16);
        unsigned lp = cvt2bf(x - __uint_as_float(xu & 0xffff0000u), 0.f);
        Wlo[n * AST + k] = (unsigned short)(lp & 0xffff);
    }
    if (t < DD) {
        colsum[t] = 0.f; colsq[t] = 0.f; bias_s[t] = __ldg(&bias[t]);
        if (doBN) {
            const float inv_n = 1.0f / (float)NND;
            float mu = statsIn[t] * inv_n;
            float var = statsIn[DD + t] * inv_n - mu * mu;
            float s = __ldg(&gam[t]) * rsqrtf(var + BN_EPS);
            scA[t] = s;
            shA[t] = __ldg(&bet[t]) - mu * s;
        }
    }

    for (int ti = blockIdx.x; ti < NT; ti += gridDim.x) {
        CP_WAIT0();
        __syncthreads();   // staging arrived everywhere; prior compute done

        // split staging (fp32) -> Ahi/Alo bf16, optional BN+relu
#pragma unroll
        for (int i = 0; i < 16; i++) {
            int fi = t + i * 256;
            int row = fi >> 5, kq = fi & 31;
            float4 v = ((const float4*)Sg)[fi];
            if (doBN) {
                int ch = kq * 4;
                v.x = fmaxf(v.x * scA[ch] + shA[ch], 0.f);
                v.y = fmaxf(v.y * scA[ch + 1] + shA[ch + 1], 0.f);
                v.z = fmaxf(v.z * scA[ch + 2] + shA[ch + 2], 0.f);
                v.w = fmaxf(v.w * scA[ch + 3] + shA[ch + 3], 0.f);
            }
            unsigned hx = __byte_perm(__float_as_uint(v.x), __float_as_uint(v.y), 0x7632);
            unsigned hy = __byte_perm(__float_as_uint(v.z), __float_as_uint(v.w), 0x7632);
            unsigned lx = cvt2bf(v.x - __uint_as_float(__float_as_uint(v.x) & 0xffff0000u),
                                 v.y - __uint_as_float(__float_as_uint(v.y) & 0xffff0000u));
            unsigned ly = cvt2bf(v.z - __uint_as_float(__float_as_uint(v.z) & 0xffff0000u),
                                 v.w - __uint_as_float(__float_as_uint(v.w) & 0xffff0000u));
            *(uint2*)&Ahi[row * AST + kq * 4] = make_uint2(hx, hy);
            *(uint2*)&Alo[row * AST + kq * 4] = make_uint2(lx, ly);
        }
        __syncthreads();   // staging consumed, A tiles ready

        // prefetch next tile into staging (overlaps MMA below)
        int tn = ti + gridDim.x;
        if (tn < NT) {
#pragma unroll
            for (int i = 0; i < 16; i++) {
                int fi = t + i * 256;
                int row = fi >> 5, kq = fi & 31;
                int grow = tn * 128 + row;
                bool valid = grow < NND;
                const float4* gp = (const float4*)A + ((size_t)(valid ? grow : 0) * 32 + kq);
                cpasync16(sgBase + fi * 16, gp, valid ? 16 : 0);
            }
            CP_COMMIT();
        }

        float c[16][4];
#pragma unroll
        for (int i = 0; i < 16; i++)
#pragma unroll
            for (int j = 0; j < 4; j++) c[i][j] = 0.f;

#pragma unroll
        for (int ks = 0; ks < 8; ks++) {
            int k0 = ks * 16;
            unsigned ah[2][4], al[2][4];
#pragma unroll
            for (int m = 0; m < 2; m++) {
                int r0 = wr + m * 16;
                ah[m][0] = *(unsigned*)&Ahi[(r0 + g) * AST + k0 + q * 2];
                ah[m][1] = *(unsigned*)&Ahi[(r0 + g + 8) * AST + k0 + q * 2];
                ah[m][2] = *(unsigned*)&Ahi[(r0 + g) * AST + k0 + 8 + q * 2];
                ah[m][3] = *(unsigned*)&Ahi[(r0 + g + 8) * AST + k0 + 8 + q * 2];
                al[m][0] = *(unsigned*)&Alo[(r0 + g) * AST + k0 + q * 2];
                al[m][1] = *(unsigned*)&Alo[(r0 + g + 8) * AST + k0 + q * 2];
                al[m][2] = *(unsigned*)&Alo[(r0 + g) * AST + k0 + 8 + q * 2];
                al[m][3] = *(unsigned*)&Alo[(r0 + g + 8) * AST + k0 + 8 + q * 2];
            }
            unsigned bh[8][2], bl[8][2];
#pragma unroll
            for (int n = 0; n < 8; n++) {
                int n0 = wc + n * 8 + g;
                bh[n][0] = *(unsigned*)&Whi[n0 * AST + k0 + q * 2];
                bh[n][1] = *(unsigned*)&Whi[n0 * AST + k0 + 8 + q * 2];
                bl[n][0] = *(unsigned*)&Wlo[n0 * AST + k0 + q * 2];
                bl[n][1] = *(unsigned*)&Wlo[n0 * AST + k0 + 8 + q * 2];
            }
#pragma unroll
            for (int m = 0; m < 2; m++)
#pragma unroll
                for (int n = 0; n < 8; n++) {
                    mma16816(c[m * 8 + n], ah[m], bh[n]);
                    mma16816(c[m * 8 + n], al[m], bh[n]);
                    mma16816(c[m * 8 + n], ah[m], bl[n]);
                }
        }

        // epilogue: bias, store Z, fused output column stats
#pragma unroll
        for (int n = 0; n < 8; n++) {
            int col = wc + n * 8 + q * 2;
            float b0 = bias_s[col], b1 = bias_s[col + 1];
            float s0 = 0.f, s1 = 0.f, q0 = 0.f, q1 = 0.f;
#pragma unroll
            for (int m = 0; m < 2; m++) {
                int row0 = ti * 128 + wr + m * 16 + g;
                float* cf = c[m * 8 + n];
                float v0 = cf[0] + b0, v1 = cf[1] + b1;
                float v2 = cf[2] + b0, v3 = cf[3] + b1;
                if (row0 < NND) {
                    *(float2*)&Z[(size_t)row0 * DD + col] = make_float2(v0, v1);
                    s0 += v0; s1 += v1; q0 += v0 * v0; q1 += v1 * v1;
                }
                if (row0 + 8 < NND) {
                    *(float2*)&Z[(size_t)(row0 + 8) * DD + col] = make_float2(v2, v3);
                    s0 += v2; s1 += v3; q0 += v2 * v2; q1 += v3 * v3;
                }
            }
#pragma unroll
            for (int o = 4; o < 32; o <<= 1) {
                s0 += __shfl_xor_sync(0xffffffffu, s0, o);
                s1 += __shfl_xor_sync(0xffffffffu, s1, o);
                q0 += __shfl_xor_sync(0xffffffffu, q0, o);
                q1 += __shfl_xor_sync(0xffffffffu, q1, o);
            }
            if (lane < 4) {
                atomicAdd(&colsum[col], s0);
                atomicAdd(&colsum[col + 1], s1);
                atomicAdd(&colsq[col], q0);
                atomicAdd(&colsq[col + 1], q1);
            }
        }
    }

    __syncthreads();
    if (t < DD) {
        atomicAdd(&statsOut[t], colsum[t]);
        atomicAdd(&statsOut[DD + t], colsq[t]);
    }
}

// ---------------- BN-on-the-fly segmented graph pooling (no H write) ----------------
__global__ void k_pool(float* __restrict__ pg, const float* __restrict__ Z,
                       const float* __restrict__ gam, const float* __restrict__ bet,
                       const float* __restrict__ stats, const int* __restrict__ gids) {
    __shared__ float sc[DD], sh[DD];
    int t = threadIdx.x;
    if (t < DD) {
        const float inv_n = 1.0f / (float)NND;
        float mu = stats[t] * inv_n;
        float var = stats[DD + t] * inv_n - mu * mu;
        float s = __ldg(&gam[t]) * rsqrtf(var + BN_EPS);
        sc[t] = s;
        sh[t] = __ldg(&bet[t]) - mu * s;
    }
    __syncthreads();
    int warp = (blockIdx.x * blockDim.x + t) >> 5;
    int lane = t & 31;
    int r0 = warp * 32;
    if (r0 >= NND) return;
    int r1 = min(r0 + 32, NND);
    int ch = lane * 4;
    float c0 = sc[ch], c1 = sc[ch + 1], c2 = sc[ch + 2], c3 = sc[ch + 3];
    float h0 = sh[ch], h1 = sh[ch + 1], h2 = sh[ch + 2], h3 = sh[ch + 3];
    int cur = __ldg(&gids[r0]);
    float4 acc = make_float4(0.f, 0.f, 0.f, 0.f);
    for (int r = r0; r < r1; r++) {
        int gid = __ldg(&gids[r]);
        if (gid != cur) {
            red_add_v4(&pg[cur * DD + ch], acc);
            acc = make_float4(0.f, 0.f, 0.f, 0.f);
            cur = gid;
        }
        float4 v = ((const float4*)Z)[r * 32 + lane];
        acc.x += fmaxf(v.x * c0 + h0, 0.f);
        acc.y += fmaxf(v.y * c1 + h1, 0.f);
        acc.z += fmaxf(v.z * c2 + h2, 0.f);
        acc.w += fmaxf(v.w * c3 + h3, 0.f);
    }
    red_add_v4(&pg[cur * DD + ch], acc);
}

// segmented pooling for layer-0 (h = x, no BN)
__global__ void k_gpool(float* __restrict__ pg, const float* __restrict__ h,
                        const int* __restrict__ gids) {
    int warp = (blockIdx.x * blockDim.x + threadIdx.x) >> 5;
    int lane = threadIdx.x & 31;
    int r0 = warp * 32;
    if (r0 >= NND) return;
    int r1 = min(r0 + 32, NND);
    int ch = lane * 4;
    int cur = __ldg(&gids[r0]);
    float4 acc = make_float4(0.f, 0.f, 0.f, 0.f);
    for (int r = r0; r < r1; r++) {
        int gid = __ldg(&gids[r]);
        if (gid != cur) {
            red_add_v4(&pg[cur * DD + ch], acc);
            acc = make_float4(0.f, 0.f, 0.f, 0.f);
            cur = gid;
        }
        float4 v = ((const float4*)h)[r * 32 + lane];
        acc.x += v.x; acc.y += v.y; acc.z += v.z; acc.w += v.w;
    }
    red_add_v4(&pg[cur * DD + ch], acc);
}

__global__ void k_readout(float* __restrict__ out,
                          const float* __restrict__ predW,
                          const float* __restrict__ predb) {
    int g = blockIdx.x;
    int o = threadIdx.x;
    float acc = 0.f;
#pragma unroll
    for (int l = 0; l < NL + 1; l++) {
        const float* pgrow = &g_pg[l * NG * DD + g * DD];
        const float* Wl = &predW[l * DD * OUTD];
        float a = 0.f;
        for (int k = 0; k < DD; k++)
            a += pgrow[k] * __ldg(&Wl[k * OUTD + o]);
        acc += a + __ldg(&predb[l * OUTD + o]);
    }
    out[g * OUTD + o] = acc;
}

// ---------------- launch ----------------
extern "C" void kernel_launch(void* const* d_in, const int* in_sizes, int n_in,
                              void* d_out, int out_size) {
    const float* x     = (const float*)d_in[0];
    const int* esrc    = (const int*)d_in[1];
    const int* edst    = (const int*)d_in[2];
    const int* gids    = (const int*)d_in[3];
    const float* eps   = (const float*)d_in[4];
    const float* W1    = (const float*)d_in[5];
    const float* b1    = (const float*)d_in[6];
    const float* g1    = (const float*)d_in[7];
    const float* be1   = (const float*)d_in[8];
    const float* W2    = (const float*)d_in[9];
    const float* b2    = (const float*)d_in[10];
    const float* g2    = (const float*)d_in[11];
    const float* be2   = (const float*)d_in[12];
    const float* predW = (const float*)d_in[13];
    const float* predb = (const float*)d_in[14];
    float* out = (float*)d_out;

    float *P, *Z, *Z2, *stats, *pg;
    int* deg;
    cudaGetSymbolAddress((void**)&P, g_P);
    cudaGetSymbolAddress((void**)&Z, g_Z);
    cudaGetSymbolAddress((void**)&Z2, g_Z2);
    cudaGetSymbolAddress((void**)&stats, g_stats);
    cudaGetSymbolAddress((void**)&pg, g_pg);
    cudaGetSymbolAddress((void**)&deg, g_deg);
    float* s0 = stats;
    float* s1 = stats + 2 * DD;

    const int smem_mm = 4 * DD * AST * (int)sizeof(unsigned short) + 65536;  // 200704
    static bool attr_set = false;
    if (!attr_set) {
        cudaFuncSetAttribute(k_mm, cudaFuncAttributeMaxDynamicSharedMemorySize, smem_mm);
        attr_set = true;
    }

    const int gridEdge = (NE + 255) / 256;
    const int nWarps = (NND + 31) / 32;
    const int gridSeg = (nWarps * 32 + 255) / 256;

    // CSR build (once; shared by all 4 layers)
    cudaMemsetAsync(deg, 0, sizeof(int) * NND);
    k_hist<<<gridEdge, 256>>>(edst);
    k_scan<<<1, 1024>>>();
    k_scatter<<<gridEdge, 256>>>(esrc, edst);

    // layer-0 graph pooling
    cudaMemsetAsync(pg, 0, sizeof(float) * (NL + 1) * NG * DD);
    k_gpool<<<gridSeg, 256>>>(pg, x, gids);

    for (int l = 0; l < NL; l++) {
        if (l == 0)
            k_agg<<<(NND + 7) / 8, 256>>>(P, x, eps, l, nullptr, nullptr, nullptr);
        else
            k_agg<<<(NND + 7) / 8, 256>>>(P, Z2, eps, l,
                                          g2 + (l - 1) * DD, be2 + (l - 1) * DD, s1);

        cudaMemsetAsync(s0, 0, sizeof(float) * 2 * DD);
        k_mm<<<148, 256, smem_mm>>>(Z, P, W1 + l * DD * DD, b1 + l * DD,
                                    nullptr, nullptr, nullptr, s0);

        cudaMemsetAsync(s1, 0, sizeof(float) * 2 * DD);
        k_mm<<<148, 256, smem_mm>>>(Z2, Z, W2 + l * DD * DD, b2 + l * DD,
                                    g1 + l * DD, be1 + l * DD, s0, s1);

        k_pool<<<gridSeg, 256>>>(pg + (l + 1) * NG * DD, Z2,
                                 g2 + l * DD, be2 + l * DD, s1, gids);
    }

    k_readout<<<NG, OUTD>>>(out, predW, predb);
}